// round 1
// baseline (speedup 1.0000x reference)
#include <cuda_runtime.h>
#include <math.h>

// Problem constants
#define CELLS_PER_BLOCK 256
#define SLOTS 15
#define FLOATS_PER_BLOCK (CELLS_PER_BLOCK * SLOTS)          // 3840 floats = 15360 B (16B aligned)
#define VEC4_PER_BLOCK   (FLOATS_PER_BLOCK / 4)             // 960 float4
#define EPSF 1e-9f

// double-precision scratch accumulator (device global: no allocation allowed)
__device__ double g_loss_accum;

__global__ void yolo_zero_kernel(float* out) {
    if (threadIdx.x == 0) {
        g_loss_accum = 0.0;
        out[0] = 0.0f;
    }
}

__global__ __launch_bounds__(CELLS_PER_BLOCK)
void yolo_loss_kernel(const float* __restrict__ o,
                      const float* __restrict__ t) {
    __shared__ float so[FLOATS_PER_BLOCK];
    __shared__ float st[FLOATS_PER_BLOCK];
    __shared__ float warp_part[CELLS_PER_BLOCK / 32];

    const int tid = threadIdx.x;
    const long long base = (long long)blockIdx.x * FLOATS_PER_BLOCK;

    // Coalesced staging: 960 float4 per tensor, 256 threads x 4 iters (last partial)
    const float4* o4 = reinterpret_cast<const float4*>(o + base);
    const float4* t4 = reinterpret_cast<const float4*>(t + base);
    float4* so4 = reinterpret_cast<float4*>(so);
    float4* st4 = reinterpret_cast<float4*>(st);

#pragma unroll
    for (int i = 0; i < 4; i++) {
        int idx = tid + i * CELLS_PER_BLOCK;
        if (idx < VEC4_PER_BLOCK) {
            so4[idx] = o4[idx];
            st4[idx] = t4[idx];
        }
    }
    __syncthreads();

    // One thread per cell; stride-15 smem reads are bank-conflict-free
    const float* co = so + tid * SLOTS;
    const float* ct = st + tid * SLOTS;

    float loss = 0.0f;
    const float o0 = co[0];
    if (o0 != 0.0f) {
        // coordinate loss: x + sqrt(w) + sqrt(h) terms
        float d0 = o0 - ct[0];
        float dw = sqrtf(co[2]) - sqrtf(ct[2]);
        float dh = sqrtf(co[3]) - sqrtf(ct[3]);
        float coord = d0 * d0 + dw * dw + dh * dh;

        // BCE on confidence slot
        float tc = ct[4];
        float oc = co[4];
        float conf = -(tc * logf(oc + EPSF) + (1.0f - tc) * logf(1.0f - oc + EPSF));

        // class loss over slots 5..13
        float cls = 0.0f;
#pragma unroll
        for (int k = 5; k < 14; k++) {
            float d = ct[k] - co[k];
            cls = fmaf(d, d, cls);
        }
        loss = coord + conf + cls;
    }

    // warp reduce (pairwise tree)
#pragma unroll
    for (int off = 16; off > 0; off >>= 1)
        loss += __shfl_xor_sync(0xFFFFFFFFu, loss, off);

    const int wid = tid >> 5;
    const int lid = tid & 31;
    if (lid == 0) warp_part[wid] = loss;
    __syncthreads();

    if (wid == 0) {
        float v = (lid < (CELLS_PER_BLOCK / 32)) ? warp_part[lid] : 0.0f;
#pragma unroll
        for (int off = 4; off > 0; off >>= 1)
            v += __shfl_xor_sync(0xFFFFFFFFu, v, off);
        if (lid == 0)
            atomicAdd(&g_loss_accum, (double)v);
    }
}

__global__ void yolo_finish_kernel(float* out) {
    if (threadIdx.x == 0)
        out[0] = (float)g_loss_accum;
}

extern "C" void kernel_launch(void* const* d_in, const int* in_sizes, int n_in,
                              void* d_out, int out_size) {
    const float* o = (const float*)d_in[0];
    const float* t = (const float*)d_in[1];
    float* out = (float*)d_out;

    const long long total_floats = (long long)in_sizes[0];     // 512 * 47040
    const long long total_cells = total_floats / SLOTS;        // 1,605,632
    const int nblocks = (int)((total_cells + CELLS_PER_BLOCK - 1) / CELLS_PER_BLOCK); // 6272

    yolo_zero_kernel<<<1, 32>>>(out);
    yolo_loss_kernel<<<nblocks, CELLS_PER_BLOCK>>>(o, t);
    yolo_finish_kernel<<<1, 32>>>(out);
}